// round 9
// baseline (speedup 1.0000x reference)
#include <cuda_runtime.h>
#include <cuda_bf16.h>
#include <cstdint>

#define B_ 64
#define S_ 2048
#define H_ 512

// ---------------- scratch (device globals; no allocation allowed) ----------
__device__ float g_c[B_ * H_];                       // e_fin[b,k] + attn_b[k]
__device__ float g_scores_part[4 * B_ * S_];         // per-k-tile partial scores
__device__ float g_weights[B_ * S_];                 // softmax weights
__device__ float g_ctx_part[16 * B_ * H_];           // per-s-chunk partial context
__device__ __nv_bfloat16 g_enc_hi[(size_t)B_ * S_ * H_];   // 128 MB
__device__ __nv_bfloat16 g_enc_lo[(size_t)B_ * S_ * H_];   // 128 MB
__device__ __nv_bfloat16 g_w_hi[H_ * H_];
__device__ __nv_bfloat16 g_w_lo[H_ * H_];

// ---------------- helpers ---------------------------------------------------
__device__ __forceinline__ uint32_t smem_u32(const void* p) {
    uint32_t a;
    asm("{ .reg .u64 t; cvta.to.shared.u64 t, %1; cvt.u32.u64 %0, t; }" : "=r"(a) : "l"(p));
    return a;
}
__device__ __forceinline__ void cp16(uint32_t dst, const void* src) {
    asm volatile("cp.async.cg.shared.global [%0], [%1], 16;" :: "r"(dst), "l"(src) : "memory");
}
#define CP_COMMIT() asm volatile("cp.async.commit_group;" ::: "memory")

__device__ __forceinline__ void ldsm4(uint32_t* r, uint32_t addr) {
    asm volatile("ldmatrix.sync.aligned.m8n8.x4.shared.b16 {%0,%1,%2,%3}, [%4];"
                 : "=r"(r[0]), "=r"(r[1]), "=r"(r[2]), "=r"(r[3]) : "r"(addr));
}
__device__ __forceinline__ void mma16816(float* d, const uint32_t* a,
                                         uint32_t b0, uint32_t b1) {
    asm volatile(
        "mma.sync.aligned.m16n8k16.row.col.f32.bf16.bf16.f32 "
        "{%0,%1,%2,%3}, {%4,%5,%6,%7}, {%8,%9}, {%0,%1,%2,%3};"
        : "+f"(d[0]), "+f"(d[1]), "+f"(d[2]), "+f"(d[3])
        : "r"(a[0]), "r"(a[1]), "r"(a[2]), "r"(a[3]), "r"(b0), "r"(b1));
}

__device__ __forceinline__ float fast_tanh(float x) {
    x = fminf(fmaxf(x, -15.f), 15.f);
    float e = __expf(2.f * x);
    return __fdividef(e - 1.f, e + 1.f);
}

// ---------------- K0a: enc f32 -> bf16 hi/lo split --------------------------
__global__ void convert_enc_kernel(const float* __restrict__ enc) {
    size_t i = (size_t)blockIdx.x * 256 + threadIdx.x;
    float4 x = ((const float4*)enc)[i];
    float v[4] = {x.x, x.y, x.z, x.w};
    ushort4 ho, lo;
    unsigned short* hp = &ho.x;
    unsigned short* lp = &lo.x;
#pragma unroll
    for (int j = 0; j < 4; j++) {
        __nv_bfloat16 h = __float2bfloat16(v[j]);
        __nv_bfloat16 l = __float2bfloat16(v[j] - __bfloat162float(h));
        hp[j] = __bfloat16_as_ushort(h);
        lp[j] = __bfloat16_as_ushort(l);
    }
    ((ushort4*)g_enc_hi)[i] = ho;
    ((ushort4*)g_enc_lo)[i] = lo;
}

// ---------------- K0b: w_enc f32 -> bf16 hi/lo ------------------------------
__global__ void convert_w_kernel(const float* __restrict__ attn_w) {
    int idx = blockIdx.x * 256 + threadIdx.x;
    int k = idx >> 9, h = idx & 511;
    float x = attn_w[(size_t)k * (2 * H_) + h];          // w_enc = attn_w[:, :H]
    __nv_bfloat16 hi = __float2bfloat16(x);
    g_w_hi[idx] = hi;
    g_w_lo[idx] = __float2bfloat16(x - __bfloat162float(hi));
}

// ---------------- K1: c[b,k] = fin[b]·attn_w[k, H:] + b[k] ------------------
__global__ void cfin_kernel(const float* __restrict__ fin,
                            const float* __restrict__ attn_w,
                            const float* __restrict__ attn_b) {
    __shared__ float fs[H_];
    const int b = blockIdx.x;
    const int k = threadIdx.x;
    fs[k] = fin[b * H_ + k];
    __syncthreads();
    const float* w = attn_w + (size_t)k * (2 * H_) + H_;
    float s = attn_b[k];
#pragma unroll 8
    for (int h = 0; h < H_; h++) s = fmaf(fs[h], w[h], s);
    g_c[b * H_ + k] = s;
}

// ---------------- K2: PTX mma bf16x3 GEMM + tanh/v epilogue -----------------
// CTA 128(s) x 128(k); 16 warps as 4(M) x 4(N); warp tile 32x32.
// K=512 in 8 chunks of KC=64; 3-stage cp.async; XOR-swizzled smem;
// fragment double-buffering across kk steps; hoisted swizzle addressing.
static constexpr int KC = 64;                        // 64 bf16 = 128B rows
static constexpr int MAT_B = 128 * 128;              // 16384 B per matrix tile
static constexpr int STAGE_B = 4 * MAT_B;            // 65536 (Ah, Al, Bh, Bl)
static constexpr int NSTAGE = 3;
static constexpr int CV_OFF = NSTAGE * STAGE_B;      // 196608
static constexpr int SMEM_NEED = CV_OFF + 1024;      // + c[128], v[128]
static constexpr int ELD = 132;                      // e-tile stride (f32)

// physical byte offset of logical (row r, 16B-chunk c) inside a 128x128B tile
__device__ __forceinline__ uint32_t sw(int r, int c) {
    return (uint32_t)(r * 128 + (((c) ^ (r & 7)) << 4));
}

__device__ __forceinline__ void fill_chunk(uint32_t sbase, int stage, int ck,
                                           int mt, int kt, int tid) {
    const uint32_t tb = sbase + stage * STAGE_B;
    const char* srcs[4] = {
        (const char*)g_enc_hi + ((size_t)mt * 128) * 1024,
        (const char*)g_enc_lo + ((size_t)mt * 128) * 1024,
        (const char*)g_w_hi   + ((size_t)kt * 128) * 1024,
        (const char*)g_w_lo   + ((size_t)kt * 128) * 1024 };
#pragma unroll
    for (int i = 0; i < 8; i++) {
        int id = i * 512 + tid;          // 0..4095
        int mat = id >> 10;
        int rem = id & 1023;
        int r = rem >> 3, c = rem & 7;
        cp16(tb + mat * MAT_B + sw(r, c),
             srcs[mat] + (size_t)r * 1024 + ck * 128 + c * 16);
    }
}

__global__ __launch_bounds__(512, 1)
void scores_mma_kernel(const float* __restrict__ v_w) {
    extern __shared__ char smem[];
    const uint32_t sbase = smem_u32(smem);
    const int tid = threadIdx.x;
    const int wid = tid >> 5, lane = tid & 31;
    const int kt = blockIdx.x;        // 0..3   (k tile of 128)
    const int mt = blockIdx.y;        // 0..1023 (s tile of 128 over B*S)
    const int b  = mt >> 4;
    const int wm = wid & 3;           // warp M index (4)
    const int wn = wid >> 2;          // warp N index (4)

    float* c_s = (float*)(smem + CV_OFF);
    float* v_s = (float*)(smem + CV_OFF + 512);
    if (tid < 128) {
        c_s[tid] = g_c[b * H_ + kt * 128 + tid];
        v_s[tid] = v_w[kt * 128 + tid];
    }

    float acc[2][4][4];
#pragma unroll
    for (int i = 0; i < 2; i++)
#pragma unroll
        for (int j = 0; j < 4; j++)
#pragma unroll
            for (int t = 0; t < 4; t++) acc[i][j][t] = 0.f;

    fill_chunk(sbase, 0, 0, mt, kt, tid); CP_COMMIT();
    fill_chunk(sbase, 1, 1, mt, kt, tid); CP_COMMIT();

    // hoisted swizzle components:
    //   addr(row, c16) = base + row*128 + ((c16 ^ (lane&7)) << 4)
    // rows of a lane's ldsm differ only in the >=128 part, so the XOR term is a
    // single per-lane per-kk constant offv[kk]; bases are 4 adds per chunk.
    const int lrow_a = wm * 32 + (lane & 15);
    const int lrow_b = wn * 32 + (lane & 15);
    const int lchi = lane >> 4;
    const int qv = lane & 7;
    uint32_t offv[4];
#pragma unroll
    for (int kk = 0; kk < 4; kk++) offv[kk] = (uint32_t)(((kk * 2 + lchi) ^ qv) << 4);

    // fragment double buffer: [slot][i][4]
    uint32_t ah[2][2][4], al[2][2][4], bh[2][2][4], bl[2][2][4];

    int buf = 0;
    for (int ck = 0; ck < 8; ck++) {
        if (ck < 6) asm volatile("cp.async.wait_group 1;" ::: "memory");
        else        asm volatile("cp.async.wait_group 0;" ::: "memory");
        __syncthreads();
        if (ck + 2 < 8) {
            int nbuf = buf + 2; if (nbuf >= 3) nbuf -= 3;
            fill_chunk(sbase, nbuf, ck + 2, mt, kt, tid);
            CP_COMMIT();
        }

        const uint32_t stb = sbase + buf * STAGE_B;
        const uint32_t bAh = stb + (uint32_t)(lrow_a * 128);
        const uint32_t bAl = bAh + MAT_B;
        const uint32_t bBh = stb + 2 * MAT_B + (uint32_t)(lrow_b * 128);
        const uint32_t bBl = bBh + MAT_B;

#define LD_GROUP(slot, off)                                   \
        do {                                                  \
            ldsm4(ah[slot][0], bAh + (off));                  \
            ldsm4(ah[slot][1], bAh + 2048 + (off));           \
            ldsm4(al[slot][0], bAl + (off));                  \
            ldsm4(al[slot][1], bAl + 2048 + (off));           \
            ldsm4(bh[slot][0], bBh + (off));                  \
            ldsm4(bh[slot][1], bBh + 2048 + (off));           \
            ldsm4(bl[slot][0], bBl + (off));                  \
            ldsm4(bl[slot][1], bBl + 2048 + (off));           \
        } while (0)

#define MMA_GROUP(slot)                                                         \
        do {                                                                    \
            _Pragma("unroll")                                                   \
            for (int i = 0; i < 2; i++)                                         \
                _Pragma("unroll")                                               \
                for (int j = 0; j < 2; j++) {                                   \
                    mma16816(acc[i][j * 2 + 0], ah[slot][i], bh[slot][j][0], bh[slot][j][2]); \
                    mma16816(acc[i][j * 2 + 1], ah[slot][i], bh[slot][j][1], bh[slot][j][3]); \
                }                                                               \
            _Pragma("unroll")                                                   \
            for (int i = 0; i < 2; i++)                                         \
                _Pragma("unroll")                                               \
                for (int j = 0; j < 2; j++) {                                   \
                    mma16816(acc[i][j * 2 + 0], ah[slot][i], bl[slot][j][0], bl[slot][j][2]); \
                    mma16816(acc[i][j * 2 + 1], ah[slot][i], bl[slot][j][1], bl[slot][j][3]); \
                }                                                               \
            _Pragma("unroll")                                                   \
            for (int i = 0; i < 2; i++)                                         \
                _Pragma("unroll")                                               \
                for (int j = 0; j < 2; j++) {                                   \
                    mma16816(acc[i][j * 2 + 0], al[slot][i], bh[slot][j][0], bh[slot][j][2]); \
                    mma16816(acc[i][j * 2 + 1], al[slot][i], bh[slot][j][1], bh[slot][j][3]); \
                }                                                               \
        } while (0)

        LD_GROUP(0, offv[0]);
        LD_GROUP(1, offv[1]);
        MMA_GROUP(0);
        LD_GROUP(0, offv[2]);
        MMA_GROUP(1);
        LD_GROUP(1, offv[3]);
        MMA_GROUP(0);
        MMA_GROUP(1);

        buf++; if (buf >= 3) buf = 0;
    }

    // ---- epilogue: acc -> e_s (stride 132), then row-sum tanh(e+c)*v -------
    float* e_s = (float*)smem;          // 128 x 132 f32 = 67.6KB (stages dead)
    __syncthreads();
#pragma unroll
    for (int i = 0; i < 2; i++)
#pragma unroll
        for (int j = 0; j < 4; j++) {
            const int row = wm * 32 + i * 16 + (lane >> 2);
            const int col = wn * 32 + j * 8 + (lane & 3) * 2;
            *(float2*)&e_s[row * ELD + col]       = make_float2(acc[i][j][0], acc[i][j][1]);
            *(float2*)&e_s[(row + 8) * ELD + col] = make_float2(acc[i][j][2], acc[i][j][3]);
        }
    __syncthreads();

    const int r = tid >> 2;            // row 0..127
    const int q = tid & 3;             // column quarter
    float s = 0.f;
#pragma unroll 8
    for (int j = 0; j < 32; j++) {
        const int k = q * 32 + ((j + r + q * 8) & 31);
        s += fast_tanh(e_s[r * ELD + k] + c_s[k]) * v_s[k];
    }
    s += __shfl_xor_sync(0xffffffffu, s, 1);
    s += __shfl_xor_sync(0xffffffffu, s, 2);
    if (q == 0)
        g_scores_part[(size_t)kt * (B_ * S_) + mt * 128 + r] = s;
}

// ---------------- K3: softmax over S per batch ------------------------------
__global__ void softmax_kernel() {
    const int b = blockIdx.x;
    const int tid = threadIdx.x;   // 256
    __shared__ float sbuf[256];

    float m = -1e30f;
    for (int i = tid; i < S_; i += 256) {
        float v = g_scores_part[0 * B_ * S_ + b * S_ + i]
                + g_scores_part[1 * B_ * S_ + b * S_ + i]
                + g_scores_part[2 * B_ * S_ + b * S_ + i]
                + g_scores_part[3 * B_ * S_ + b * S_ + i];
        g_weights[b * S_ + i] = v;
        m = fmaxf(m, v);
    }
    sbuf[tid] = m; __syncthreads();
    for (int o = 128; o > 0; o >>= 1) {
        if (tid < o) sbuf[tid] = fmaxf(sbuf[tid], sbuf[tid + o]);
        __syncthreads();
    }
    m = sbuf[0]; __syncthreads();

    float sum = 0.f;
    for (int i = tid; i < S_; i += 256) {
        float e = __expf(g_weights[b * S_ + i] - m);
        g_weights[b * S_ + i] = e;
        sum += e;
    }
    sbuf[tid] = sum; __syncthreads();
    for (int o = 128; o > 0; o >>= 1) {
        if (tid < o) sbuf[tid] += sbuf[tid + o];
        __syncthreads();
    }
    float inv = __fdividef(1.f, sbuf[0]);
    for (int i = tid; i < S_; i += 256) g_weights[b * S_ + i] *= inv;
}

// ---------------- K4: partial context per 128-s chunk -----------------------
__global__ void context_kernel(const float* __restrict__ enc) {
    const int sc = blockIdx.x;   // 0..15
    const int b  = blockIdx.y;
    const int tid = threadIdx.x; // 512
    __shared__ float ws[128];
    if (tid < 128) ws[tid] = g_weights[b * S_ + sc * 128 + tid];
    __syncthreads();
    const float* e = enc + ((size_t)b * S_ + sc * 128) * H_ + tid;
    float acc = 0.f;
#pragma unroll 8
    for (int s = 0; s < 128; s++) acc = fmaf(ws[s], e[(size_t)s * H_], acc);
    g_ctx_part[((size_t)sc * B_ + b) * H_ + tid] = acc;
}

// ---------------- K5: reduce partial contexts -------------------------------
__global__ void reduce_ctx(float* __restrict__ out) {
    int i = blockIdx.x * 256 + threadIdx.x;
    float s = 0.f;
#pragma unroll
    for (int ch = 0; ch < 16; ch++) s += g_ctx_part[(size_t)ch * B_ * H_ + i];
    out[i] = s;
}

extern "C" void kernel_launch(void* const* d_in, const int* in_sizes, int n_in,
                              void* d_out, int out_size) {
    const float* enc    = (const float*)d_in[0];
    const float* fin    = (const float*)d_in[1];
    const float* attn_w = (const float*)d_in[2];
    const float* attn_b = (const float*)d_in[3];
    const float* v_w    = (const float*)d_in[4];
    float* out = (float*)d_out;

    cudaFuncSetAttribute(scores_mma_kernel,
                         cudaFuncAttributeMaxDynamicSharedMemorySize, SMEM_NEED);

    convert_enc_kernel<<<65536, 256>>>(enc);
    convert_w_kernel<<<(H_ * H_) / 256, 256>>>(attn_w);
    cfin_kernel<<<B_, H_>>>(fin, attn_w, attn_b);
    scores_mma_kernel<<<dim3(4, 1024), 512, SMEM_NEED>>>(v_w);
    softmax_kernel<<<B_, 256>>>();
    context_kernel<<<dim3(16, B_), 512>>>(enc);
    reduce_ctx<<<(B_ * H_) / 256, 256>>>(out);
}

// round 10
// speedup vs baseline: 1.2710x; 1.2710x over previous
#include <cuda_runtime.h>
#include <cuda_fp16.h>
#include <cstdint>

#define B_ 64
#define S_ 2048
#define H_ 512

// ---------------- scratch (device globals; no allocation allowed) ----------
__device__ float g_c[B_ * H_];                       // e_fin[b,k] + attn_b[k]
__device__ float g_scores_part[4 * B_ * S_];         // per-k-tile partial scores
__device__ float g_weights[B_ * S_];                 // softmax weights
__device__ float g_ctx_part[16 * B_ * H_];           // per-s-chunk partial context
__device__ __half g_enc_hi[(size_t)B_ * S_ * H_];    // 128 MB (fp16 hi only)
__device__ __half g_w_hi[H_ * H_];
__device__ __half g_w_lo[H_ * H_];

// ---------------- helpers ---------------------------------------------------
__device__ __forceinline__ uint32_t smem_u32(const void* p) {
    uint32_t a;
    asm("{ .reg .u64 t; cvta.to.shared.u64 t, %1; cvt.u32.u64 %0, t; }" : "=r"(a) : "l"(p));
    return a;
}
__device__ __forceinline__ void cp16(uint32_t dst, const void* src) {
    asm volatile("cp.async.cg.shared.global [%0], [%1], 16;" :: "r"(dst), "l"(src) : "memory");
}
#define CP_COMMIT() asm volatile("cp.async.commit_group;" ::: "memory")

__device__ __forceinline__ void ldsm4(uint32_t* r, uint32_t addr) {
    asm volatile("ldmatrix.sync.aligned.m8n8.x4.shared.b16 {%0,%1,%2,%3}, [%4];"
                 : "=r"(r[0]), "=r"(r[1]), "=r"(r[2]), "=r"(r[3]) : "r"(addr));
}
__device__ __forceinline__ void mma16816(float* d, const uint32_t* a,
                                         uint32_t b0, uint32_t b1) {
    asm volatile(
        "mma.sync.aligned.m16n8k16.row.col.f32.f16.f16.f32 "
        "{%0,%1,%2,%3}, {%4,%5,%6,%7}, {%8,%9}, {%0,%1,%2,%3};"
        : "+f"(d[0]), "+f"(d[1]), "+f"(d[2]), "+f"(d[3])
        : "r"(a[0]), "r"(a[1]), "r"(a[2]), "r"(a[3]), "r"(b0), "r"(b1));
}

__device__ __forceinline__ float fast_tanh(float x) {
    x = fminf(fmaxf(x, -15.f), 15.f);
    float e = __expf(2.f * x);
    return __fdividef(e - 1.f, e + 1.f);
}

// ---------------- K0a: enc f32 -> fp16 (hi only; lh chain dropped) ----------
__global__ void convert_enc_kernel(const float* __restrict__ enc) {
    size_t i = (size_t)blockIdx.x * 256 + threadIdx.x;   // one float4 per thread
    float4 x = ((const float4*)enc)[i];
    __half2 h01 = __floats2half2_rn(x.x, x.y);
    __half2 h23 = __floats2half2_rn(x.z, x.w);
    uint2 packed;
    packed.x = *(const uint32_t*)&h01;
    packed.y = *(const uint32_t*)&h23;
    ((uint2*)g_enc_hi)[i] = packed;
}

// ---------------- K0b: w_enc f32 -> fp16 hi/lo ------------------------------
__global__ void convert_w_kernel(const float* __restrict__ attn_w) {
    int idx = blockIdx.x * 256 + threadIdx.x;            // 262144
    int k = idx >> 9, h = idx & 511;
    float x = attn_w[(size_t)k * (2 * H_) + h];          // w_enc = attn_w[:, :H]
    __half hi = __float2half_rn(x);
    g_w_hi[idx] = hi;
    g_w_lo[idx] = __float2half_rn(x - __half2float(hi));
}

// ---------------- K1: c[b,k] = fin[b]·attn_w[k, H:] + b[k] ------------------
__global__ void cfin_kernel(const float* __restrict__ fin,
                            const float* __restrict__ attn_w,
                            const float* __restrict__ attn_b) {
    __shared__ float fs[H_];
    const int b = blockIdx.x;
    const int k = threadIdx.x;
    fs[k] = fin[b * H_ + k];
    __syncthreads();
    const float* w = attn_w + (size_t)k * (2 * H_) + H_;
    float s = attn_b[k];
#pragma unroll 8
    for (int h = 0; h < H_; h++) s = fmaf(fs[h], w[h], s);
    g_c[b * H_ + k] = s;
}

// ---------------- K2: fp16x2 mma GEMM + tanh/v epilogue ---------------------
// CTA 256(s) x 128(k); 16 warps as 4(M) x 4(N); warp tile 64x32.
// Chains: hh (a_hi x b_hi) + hl (a_hi x b_lo). K=512 in 8 chunks of 64;
// 3-stage cp.async pipeline; XOR-swizzled smem.
static constexpr int KC = 64;                        // 64 fp16 = 128B rows
static constexpr int MAT_A  = 256 * 128;             // 32768 B (A_hi)
static constexpr int MAT_BT = 128 * 128;             // 16384 B (each of Bh, Bl)
static constexpr int STAGE_B = MAT_A + 2 * MAT_BT;   // 65536
static constexpr int NSTAGE = 3;
static constexpr int CV_OFF = NSTAGE * STAGE_B;      // 196608
static constexpr int SMEM_NEED = CV_OFF + 1024;      // + c[128], v[128]
static constexpr int ELD = 132;                      // e-tile stride (f32)

// physical byte offset of logical (row r, 16B-chunk c) inside a 128B-row tile
__device__ __forceinline__ uint32_t sw(int r, int c) {
    return (uint32_t)(r * 128 + (((c) ^ (r & 7)) << 4));
}

__device__ __forceinline__ void fill_chunk(uint32_t sbase, int stage, int ck,
                                           int mt, int kt, int tid) {
    const uint32_t tb = sbase + stage * STAGE_B;
    // A_hi: 256 rows x 128B = 2048 cp16
#pragma unroll
    for (int i = 0; i < 4; i++) {
        int id = i * 512 + tid;          // 0..2047
        int r = id >> 3, c = id & 7;
        cp16(tb + sw(r, c),
             (const char*)g_enc_hi + (size_t)(mt * 256 + r) * 1024 + ck * 128 + c * 16);
    }
    // B hi+lo: 2 x 128 rows x 128B = 2048 cp16
#pragma unroll
    for (int i = 0; i < 4; i++) {
        int id = i * 512 + tid;          // 0..2047
        int mat = id >> 10;              // 0 = Bh, 1 = Bl
        int rem = id & 1023;
        int r = rem >> 3, c = rem & 7;
        cp16(tb + MAT_A + mat * MAT_BT + sw(r, c),
             (const char*)(mat ? g_w_lo : g_w_hi)
                 + (size_t)(kt * 128 + r) * 1024 + ck * 128 + c * 16);
    }
}

__global__ __launch_bounds__(512, 1)
void scores_mma_kernel(const float* __restrict__ v_w) {
    extern __shared__ char smem[];
    const uint32_t sbase = smem_u32(smem);
    const int tid = threadIdx.x;
    const int wid = tid >> 5, lane = tid & 31;
    const int kt = blockIdx.x;        // 0..3   (k tile of 128)
    const int mt = blockIdx.y;        // 0..511 (s tile of 256 over B*S)
    const int b  = mt >> 3;           // 8 s-tiles per batch
    const int wm = wid & 3;           // warp M index (4) -> 64 rows each
    const int wn = wid >> 2;          // warp N index (4) -> 32 cols each

    float* c_s = (float*)(smem + CV_OFF);
    float* v_s = (float*)(smem + CV_OFF + 512);
    if (tid < 128) {
        c_s[tid] = g_c[b * H_ + kt * 128 + tid];
        v_s[tid] = v_w[kt * 128 + tid];
    }

    float acc[4][4][4];
#pragma unroll
    for (int i = 0; i < 4; i++)
#pragma unroll
        for (int j = 0; j < 4; j++)
#pragma unroll
            for (int t = 0; t < 4; t++) acc[i][j][t] = 0.f;

    fill_chunk(sbase, 0, 0, mt, kt, tid); CP_COMMIT();
    fill_chunk(sbase, 1, 1, mt, kt, tid); CP_COMMIT();

    const int lrow_a = wm * 64 + (lane & 15);
    const int lrow_b = wn * 32 + (lane & 15);
    const int lchi = lane >> 4;
    const int qv = lane & 7;
    uint32_t offv[4];
#pragma unroll
    for (int kk = 0; kk < 4; kk++) offv[kk] = (uint32_t)(((kk * 2 + lchi) ^ qv) << 4);

    int buf = 0;
    for (int ck = 0; ck < 8; ck++) {
        if (ck < 6) asm volatile("cp.async.wait_group 1;" ::: "memory");
        else        asm volatile("cp.async.wait_group 0;" ::: "memory");
        __syncthreads();
        if (ck + 2 < 8) {
            int nbuf = buf + 2; if (nbuf >= 3) nbuf -= 3;
            fill_chunk(sbase, nbuf, ck + 2, mt, kt, tid);
            CP_COMMIT();
        }

        const uint32_t stb = sbase + buf * STAGE_B;
        const uint32_t bA  = stb + (uint32_t)(lrow_a * 128);
        const uint32_t bBh = stb + MAT_A + (uint32_t)(lrow_b * 128);
        const uint32_t bBl = bBh + MAT_BT;

#pragma unroll
        for (int kk = 0; kk < 4; kk++) {
            uint32_t a[4][4], bh[2][4], bl[2][4];
#pragma unroll
            for (int i = 0; i < 4; i++) ldsm4(a[i], bA + i * 2048 + offv[kk]);
#pragma unroll
            for (int j = 0; j < 2; j++) {
                ldsm4(bh[j], bBh + j * 2048 + offv[kk]);
                ldsm4(bl[j], bBl + j * 2048 + offv[kk]);
            }
            // chain hh (16 MMAs), then hl (16 MMAs); same-acc spacing = 16
#pragma unroll
            for (int i = 0; i < 4; i++)
#pragma unroll
                for (int j = 0; j < 2; j++) {
                    mma16816(acc[i][j * 2 + 0], a[i], bh[j][0], bh[j][2]);
                    mma16816(acc[i][j * 2 + 1], a[i], bh[j][1], bh[j][3]);
                }
#pragma unroll
            for (int i = 0; i < 4; i++)
#pragma unroll
                for (int j = 0; j < 2; j++) {
                    mma16816(acc[i][j * 2 + 0], a[i], bl[j][0], bl[j][2]);
                    mma16816(acc[i][j * 2 + 1], a[i], bl[j][1], bl[j][3]);
                }
        }
        buf++; if (buf >= 3) buf = 0;
    }

    // ---- epilogue: acc -> e_s (256 x 132), then row-sum tanh(e+c)*v --------
    float* e_s = (float*)smem;          // 256*132*4 = 135KB (stages dead)
    __syncthreads();
#pragma unroll
    for (int i = 0; i < 4; i++)
#pragma unroll
        for (int j = 0; j < 4; j++) {
            const int row = wm * 64 + i * 16 + (lane >> 2);
            const int col = wn * 32 + j * 8 + (lane & 3) * 2;
            *(float2*)&e_s[row * ELD + col]       = make_float2(acc[i][j][0], acc[i][j][1]);
            *(float2*)&e_s[(row + 8) * ELD + col] = make_float2(acc[i][j][2], acc[i][j][3]);
        }
    __syncthreads();

    const int r  = tid >> 1;           // row 0..255
    const int h2 = tid & 1;            // column half
    float s = 0.f;
#pragma unroll 8
    for (int j = 0; j < 64; j++) {
        const int k = h2 * 64 + ((j + r + h2 * 8) & 63);   // rotate vs banks
        s += fast_tanh(e_s[r * ELD + k] + c_s[k]) * v_s[k];
    }
    s += __shfl_xor_sync(0xffffffffu, s, 1);
    if (h2 == 0)
        g_scores_part[(size_t)kt * (B_ * S_) + mt * 256 + r] = s;
}

// ---------------- K3: softmax over S per batch ------------------------------
__global__ void softmax_kernel() {
    const int b = blockIdx.x;
    const int tid = threadIdx.x;   // 256
    __shared__ float sbuf[256];

    float m = -1e30f;
    for (int i = tid; i < S_; i += 256) {
        float v = g_scores_part[0 * B_ * S_ + b * S_ + i]
                + g_scores_part[1 * B_ * S_ + b * S_ + i]
                + g_scores_part[2 * B_ * S_ + b * S_ + i]
                + g_scores_part[3 * B_ * S_ + b * S_ + i];
        g_weights[b * S_ + i] = v;
        m = fmaxf(m, v);
    }
    sbuf[tid] = m; __syncthreads();
    for (int o = 128; o > 0; o >>= 1) {
        if (tid < o) sbuf[tid] = fmaxf(sbuf[tid], sbuf[tid + o]);
        __syncthreads();
    }
    m = sbuf[0]; __syncthreads();

    float sum = 0.f;
    for (int i = tid; i < S_; i += 256) {
        float e = __expf(g_weights[b * S_ + i] - m);
        g_weights[b * S_ + i] = e;
        sum += e;
    }
    sbuf[tid] = sum; __syncthreads();
    for (int o = 128; o > 0; o >>= 1) {
        if (tid < o) sbuf[tid] += sbuf[tid + o];
        __syncthreads();
    }
    float inv = __fdividef(1.f, sbuf[0]);
    for (int i = tid; i < S_; i += 256) g_weights[b * S_ + i] *= inv;
}

// ---------------- K4: partial context per 128-s chunk -----------------------
__global__ void context_kernel(const float* __restrict__ enc) {
    const int sc = blockIdx.x;   // 0..15
    const int b  = blockIdx.y;
    const int tid = threadIdx.x; // 512
    __shared__ float ws[128];
    if (tid < 128) ws[tid] = g_weights[b * S_ + sc * 128 + tid];
    __syncthreads();
    const float* e = enc + ((size_t)b * S_ + sc * 128) * H_ + tid;
    float acc = 0.f;
#pragma unroll 8
    for (int s = 0; s < 128; s++) acc = fmaf(ws[s], e[(size_t)s * H_], acc);
    g_ctx_part[((size_t)sc * B_ + b) * H_ + tid] = acc;
}

// ---------------- K5: reduce partial contexts -------------------------------
__global__ void reduce_ctx(float* __restrict__ out) {
    int i = blockIdx.x * 256 + threadIdx.x;
    float s = 0.f;
#pragma unroll
    for (int ch = 0; ch < 16; ch++) s += g_ctx_part[(size_t)ch * B_ * H_ + i];
    out[i] = s;
}

extern "C" void kernel_launch(void* const* d_in, const int* in_sizes, int n_in,
                              void* d_out, int out_size) {
    const float* enc    = (const float*)d_in[0];
    const float* fin    = (const float*)d_in[1];
    const float* attn_w = (const float*)d_in[2];
    const float* attn_b = (const float*)d_in[3];
    const float* v_w    = (const float*)d_in[4];
    float* out = (float*)d_out;

    cudaFuncSetAttribute(scores_mma_kernel,
                         cudaFuncAttributeMaxDynamicSharedMemorySize, SMEM_NEED);

    convert_enc_kernel<<<65536, 256>>>(enc);
    convert_w_kernel<<<(H_ * H_) / 256, 256>>>(attn_w);
    cfin_kernel<<<B_, H_>>>(fin, attn_w, attn_b);
    scores_mma_kernel<<<dim3(4, 512), 512, SMEM_NEED>>>(v_w);
    softmax_kernel<<<B_, 256>>>();
    context_kernel<<<dim3(16, B_), 512>>>(enc);
    reduce_ctx<<<(B_ * H_) / 256, 256>>>(out);
}

// round 12
// speedup vs baseline: 1.7485x; 1.3757x over previous
#include <cuda_runtime.h>
#include <cuda_fp16.h>
#include <cstdint>

#define B_ 64
#define S_ 2048
#define H_ 512

// ---------------- scratch (device globals; no allocation allowed) ----------
__device__ float g_c[B_ * H_];                       // e_fin[b,k] + attn_b[k]
__device__ float g_scores_part[4 * B_ * S_];         // per-k-tile partial scores
__device__ float g_weights[B_ * S_];                 // softmax weights
__device__ float g_ctx_part[16 * B_ * H_];           // per-s-chunk partial context
__device__ __half g_enc_hi[(size_t)B_ * S_ * H_];    // 128 MB (fp16)
__device__ __half g_w_hi[H_ * H_];

// ---------------- helpers ---------------------------------------------------
__device__ __forceinline__ uint32_t smem_u32(const void* p) {
    uint32_t a;
    asm("{ .reg .u64 t; cvta.to.shared.u64 t, %1; cvt.u32.u64 %0, t; }" : "=r"(a) : "l"(p));
    return a;
}
__device__ __forceinline__ void cp16(uint32_t dst, const void* src) {
    asm volatile("cp.async.cg.shared.global [%0], [%1], 16;" :: "r"(dst), "l"(src) : "memory");
}
#define CP_COMMIT() asm volatile("cp.async.commit_group;" ::: "memory")

__device__ __forceinline__ void ldsm4(uint32_t* r, uint32_t addr) {
    asm volatile("ldmatrix.sync.aligned.m8n8.x4.shared.b16 {%0,%1,%2,%3}, [%4];"
                 : "=r"(r[0]), "=r"(r[1]), "=r"(r[2]), "=r"(r[3]) : "r"(addr));
}
__device__ __forceinline__ void mma16816(float* d, const uint32_t* a,
                                         uint32_t b0, uint32_t b1) {
    asm volatile(
        "mma.sync.aligned.m16n8k16.row.col.f32.f16.f16.f32 "
        "{%0,%1,%2,%3}, {%4,%5,%6,%7}, {%8,%9}, {%0,%1,%2,%3};"
        : "+f"(d[0]), "+f"(d[1]), "+f"(d[2]), "+f"(d[3])
        : "r"(a[0]), "r"(a[1]), "r"(a[2]), "r"(a[3]), "r"(b0), "r"(b1));
}

__device__ __forceinline__ float fast_tanh(float x) {
    x = fminf(fmaxf(x, -15.f), 15.f);
    float e = __expf(2.f * x);
    return __fdividef(e - 1.f, e + 1.f);
}

// ---------------- K0a: enc f32 -> fp16 --------------------------------------
__global__ void convert_enc_kernel(const float* __restrict__ enc) {
    size_t i = (size_t)blockIdx.x * 256 + threadIdx.x;   // one float4 per thread
    float4 x = ((const float4*)enc)[i];
    __half2 h01 = __floats2half2_rn(x.x, x.y);
    __half2 h23 = __floats2half2_rn(x.z, x.w);
    uint2 packed;
    packed.x = *(const uint32_t*)&h01;
    packed.y = *(const uint32_t*)&h23;
    ((uint2*)g_enc_hi)[i] = packed;
}

// ---------------- K0b: w_enc f32 -> fp16 ------------------------------------
__global__ void convert_w_kernel(const float* __restrict__ attn_w) {
    int idx = blockIdx.x * 256 + threadIdx.x;            // 262144
    int k = idx >> 9, h = idx & 511;
    float x = attn_w[(size_t)k * (2 * H_) + h];          // w_enc = attn_w[:, :H]
    g_w_hi[idx] = __float2half_rn(x);
}

// ---------------- K1: c[b,k] = fin[b]·attn_w[k, H:] + b[k] ------------------
__global__ void cfin_kernel(const float* __restrict__ fin,
                            const float* __restrict__ attn_w,
                            const float* __restrict__ attn_b) {
    __shared__ float fs[H_];
    const int b = blockIdx.x;
    const int k = threadIdx.x;
    fs[k] = fin[b * H_ + k];
    __syncthreads();
    const float* w = attn_w + (size_t)k * (2 * H_) + H_;
    float s = attn_b[k];
#pragma unroll 8
    for (int h = 0; h < H_; h++) s = fmaf(fs[h], w[h], s);
    g_c[b * H_ + k] = s;
}

// ---------------- K2: fp16 mma GEMM + tanh/v epilogue -----------------------
// CTA 256(s) x 128(k); 16 warps as 4(M) x 4(N); warp tile 64x32.
// Single hh chain. K=512 in 8 chunks of 64; 3-stage cp.async; XOR swizzle.
static constexpr int KC = 64;                        // 64 fp16 = 128B rows
static constexpr int MAT_A  = 256 * 128;             // 32768 B (A)
static constexpr int MAT_BT = 128 * 128;             // 16384 B (B)
static constexpr int STAGE_B = MAT_A + MAT_BT;       // 49152
static constexpr int NSTAGE = 3;
static constexpr int CV_OFF = NSTAGE * STAGE_B;      // 147456
static constexpr int SMEM_NEED = CV_OFF + 1024;      // + c[128], v[128]
static constexpr int ELD = 132;                      // e-tile stride (f32)

// physical byte offset of logical (row r, 16B-chunk c) inside a 128B-row tile
__device__ __forceinline__ uint32_t sw(int r, int c) {
    return (uint32_t)(r * 128 + (((c) ^ (r & 7)) << 4));
}

__device__ __forceinline__ void fill_chunk(uint32_t sbase, int stage, int ck,
                                           int mt, int kt, int tid) {
    const uint32_t tb = sbase + stage * STAGE_B;
    // A: 256 rows x 128B = 2048 cp16
#pragma unroll
    for (int i = 0; i < 4; i++) {
        int id = i * 512 + tid;          // 0..2047
        int r = id >> 3, c = id & 7;
        cp16(tb + sw(r, c),
             (const char*)g_enc_hi + (size_t)(mt * 256 + r) * 1024 + ck * 128 + c * 16);
    }
    // B: 128 rows x 128B = 1024 cp16
#pragma unroll
    for (int i = 0; i < 2; i++) {
        int id = i * 512 + tid;          // 0..1023
        int r = id >> 3, c = id & 7;
        cp16(tb + MAT_A + sw(r, c),
             (const char*)g_w_hi + (size_t)(kt * 128 + r) * 1024 + ck * 128 + c * 16);
    }
}

__global__ __launch_bounds__(512, 1)
void scores_mma_kernel(const float* __restrict__ v_w) {
    extern __shared__ char smem[];
    const uint32_t sbase = smem_u32(smem);
    const int tid = threadIdx.x;
    const int wid = tid >> 5, lane = tid & 31;
    const int kt = blockIdx.x;        // 0..3   (k tile of 128)
    const int mt = blockIdx.y;        // 0..511 (s tile of 256 over B*S)
    const int b  = mt >> 3;           // 8 s-tiles per batch
    const int wm = wid & 3;           // warp M index (4) -> 64 rows each
    const int wn = wid >> 2;          // warp N index (4) -> 32 cols each

    float* c_s = (float*)(smem + CV_OFF);
    float* v_s = (float*)(smem + CV_OFF + 512);
    if (tid < 128) {
        c_s[tid] = g_c[b * H_ + kt * 128 + tid];
        v_s[tid] = v_w[kt * 128 + tid];
    }

    float acc[4][4][4];
#pragma unroll
    for (int i = 0; i < 4; i++)
#pragma unroll
        for (int j = 0; j < 4; j++)
#pragma unroll
            for (int t = 0; t < 4; t++) acc[i][j][t] = 0.f;

    fill_chunk(sbase, 0, 0, mt, kt, tid); CP_COMMIT();
    fill_chunk(sbase, 1, 1, mt, kt, tid); CP_COMMIT();

    const int lrow_a = wm * 64 + (lane & 15);
    const int lrow_b = wn * 32 + (lane & 15);
    const int lchi = lane >> 4;
    const int qv = lane & 7;
    uint32_t offv[4];
#pragma unroll
    for (int kk = 0; kk < 4; kk++) offv[kk] = (uint32_t)(((kk * 2 + lchi) ^ qv) << 4);

    int buf = 0;
    for (int ck = 0; ck < 8; ck++) {
        if (ck < 6) asm volatile("cp.async.wait_group 1;" ::: "memory");
        else        asm volatile("cp.async.wait_group 0;" ::: "memory");
        __syncthreads();
        if (ck + 2 < 8) {
            int nbuf = buf + 2; if (nbuf >= 3) nbuf -= 3;
            fill_chunk(sbase, nbuf, ck + 2, mt, kt, tid);
            CP_COMMIT();
        }

        const uint32_t stb = sbase + buf * STAGE_B;
        const uint32_t bA = stb + (uint32_t)(lrow_a * 128);
        const uint32_t bB = stb + MAT_A + (uint32_t)(lrow_b * 128);

#pragma unroll
        for (int kk = 0; kk < 4; kk++) {
            uint32_t a[4][4], bh[2][4];
#pragma unroll
            for (int i = 0; i < 4; i++) ldsm4(a[i], bA + i * 2048 + offv[kk]);
#pragma unroll
            for (int j = 0; j < 2; j++) ldsm4(bh[j], bB + j * 2048 + offv[kk]);
#pragma unroll
            for (int i = 0; i < 4; i++)
#pragma unroll
                for (int j = 0; j < 2; j++) {
                    mma16816(acc[i][j * 2 + 0], a[i], bh[j][0], bh[j][2]);
                    mma16816(acc[i][j * 2 + 1], a[i], bh[j][1], bh[j][3]);
                }
        }
        buf++; if (buf >= 3) buf = 0;
    }

    // ---- epilogue: acc -> e_s (256 x 132), then row-sum tanh(e+c)*v --------
    float* e_s = (float*)smem;          // 256*132*4 = 135KB (stages dead)
    __syncthreads();
#pragma unroll
    for (int i = 0; i < 4; i++)
#pragma unroll
        for (int j = 0; j < 4; j++) {
            const int row = wm * 64 + i * 16 + (lane >> 2);
            const int col = wn * 32 + j * 8 + (lane & 3) * 2;
            *(float2*)&e_s[row * ELD + col]       = make_float2(acc[i][j][0], acc[i][j][1]);
            *(float2*)&e_s[(row + 8) * ELD + col] = make_float2(acc[i][j][2], acc[i][j][3]);
        }
    __syncthreads();

    const int r  = tid >> 1;           // row 0..255
    const int h2 = tid & 1;            // column half
    float s = 0.f;
#pragma unroll 8
    for (int j = 0; j < 64; j++) {
        const int k = h2 * 64 + ((j + r + h2 * 8) & 63);   // rotate vs banks
        s += fast_tanh(e_s[r * ELD + k] + c_s[k]) * v_s[k];
    }
    s += __shfl_xor_sync(0xffffffffu, s, 1);
    if (h2 == 0)
        g_scores_part[(size_t)kt * (B_ * S_) + mt * 256 + r] = s;
}

// ---------------- K3: softmax over S per batch ------------------------------
__global__ void softmax_kernel() {
    const int b = blockIdx.x;
    const int tid = threadIdx.x;   // 256
    __shared__ float sbuf[256];

    float m = -1e30f;
    for (int i = tid; i < S_; i += 256) {
        float v = g_scores_part[0 * B_ * S_ + b * S_ + i]
                + g_scores_part[1 * B_ * S_ + b * S_ + i]
                + g_scores_part[2 * B_ * S_ + b * S_ + i]
                + g_scores_part[3 * B_ * S_ + b * S_ + i];
        g_weights[b * S_ + i] = v;
        m = fmaxf(m, v);
    }
    sbuf[tid] = m; __syncthreads();
    for (int o = 128; o > 0; o >>= 1) {
        if (tid < o) sbuf[tid] = fmaxf(sbuf[tid], sbuf[tid + o]);
        __syncthreads();
    }
    m = sbuf[0]; __syncthreads();

    float sum = 0.f;
    for (int i = tid; i < S_; i += 256) {
        float e = __expf(g_weights[b * S_ + i] - m);
        g_weights[b * S_ + i] = e;
        sum += e;
    }
    sbuf[tid] = sum; __syncthreads();
    for (int o = 128; o > 0; o >>= 1) {
        if (tid < o) sbuf[tid] += sbuf[tid + o];
        __syncthreads();
    }
    float inv = __fdividef(1.f, sbuf[0]);
    for (int i = tid; i < S_; i += 256) g_weights[b * S_ + i] *= inv;
}

// ---------------- K4: partial context per 128-s chunk (fp16 enc) ------------
__global__ void context_kernel() {
    const int sc = blockIdx.x;   // 0..15
    const int b  = blockIdx.y;
    const int tid = threadIdx.x; // 256, each handles 2 h columns
    __shared__ float ws[128];
    if (tid < 128) ws[tid] = g_weights[b * S_ + sc * 128 + tid];
    __syncthreads();
    const __half2* e = (const __half2*)(g_enc_hi + ((size_t)b * S_ + sc * 128) * H_) + tid;
    float ax = 0.f, ay = 0.f;
#pragma unroll 8
    for (int s = 0; s < 128; s++) {
        float2 v = __half22float2(e[(size_t)s * (H_ / 2)]);
        ax = fmaf(ws[s], v.x, ax);
        ay = fmaf(ws[s], v.y, ay);
    }
    float* dst = &g_ctx_part[((size_t)sc * B_ + b) * H_ + 2 * tid];
    dst[0] = ax;
    dst[1] = ay;
}

// ---------------- K5: reduce partial contexts -------------------------------
__global__ void reduce_ctx(float* __restrict__ out) {
    int i = blockIdx.x * 256 + threadIdx.x;
    float s = 0.f;
#pragma unroll
    for (int ch = 0; ch < 16; ch++) s += g_ctx_part[(size_t)ch * B_ * H_ + i];
    out[i] = s;
}

extern "C" void kernel_launch(void* const* d_in, const int* in_sizes, int n_in,
                              void* d_out, int out_size) {
    const float* enc    = (const float*)d_in[0];
    const float* fin    = (const float*)d_in[1];
    const float* attn_w = (const float*)d_in[2];
    const float* attn_b = (const float*)d_in[3];
    const float* v_w    = (const float*)d_in[4];
    float* out = (float*)d_out;

    cudaFuncSetAttribute(scores_mma_kernel,
                         cudaFuncAttributeMaxDynamicSharedMemorySize, SMEM_NEED);

    convert_enc_kernel<<<65536, 256>>>(enc);
    convert_w_kernel<<<(H_ * H_) / 256, 256>>>(attn_w);
    cfin_kernel<<<B_, H_>>>(fin, attn_w, attn_b);
    scores_mma_kernel<<<dim3(4, 512), 512, SMEM_NEED>>>(v_w);
    softmax_kernel<<<B_, 256>>>();
    context_kernel<<<dim3(16, B_), 256>>>();
    reduce_ctx<<<(B_ * H_) / 256, 256>>>(out);
}

// round 14
// speedup vs baseline: 1.9087x; 1.0916x over previous
#include <cuda_runtime.h>
#include <cuda_fp16.h>
#include <cstdint>

#define B_ 64
#define S_ 2048
#define H_ 512

// ---------------- scratch (device globals; no allocation allowed) ----------
__device__ float g_c[B_ * H_];                       // e_fin[b,k] + attn_b[k]
__device__ float g_scores_part[2 * B_ * S_];         // per-k-half partial scores
__device__ float g_weights[B_ * S_];                 // softmax weights
__device__ float g_ctx_part[16 * B_ * H_];           // per-s-chunk partial context
__device__ __half g_enc_hi[(size_t)B_ * S_ * H_];    // 128 MB (fp16)
__device__ __half g_w_hi[H_ * H_];

// ---------------- helpers ---------------------------------------------------
__device__ __forceinline__ uint32_t smem_u32(const void* p) {
    uint32_t a;
    asm("{ .reg .u64 t; cvta.to.shared.u64 t, %1; cvt.u32.u64 %0, t; }" : "=r"(a) : "l"(p));
    return a;
}
__device__ __forceinline__ void cp16(uint32_t dst, const void* src) {
    asm volatile("cp.async.cg.shared.global [%0], [%1], 16;" :: "r"(dst), "l"(src) : "memory");
}
#define CP_COMMIT() asm volatile("cp.async.commit_group;" ::: "memory")

__device__ __forceinline__ void ldsm4(uint32_t* r, uint32_t addr) {
    asm volatile("ldmatrix.sync.aligned.m8n8.x4.shared.b16 {%0,%1,%2,%3}, [%4];"
                 : "=r"(r[0]), "=r"(r[1]), "=r"(r[2]), "=r"(r[3]) : "r"(addr));
}
__device__ __forceinline__ void mma16816(float* d, const uint32_t* a,
                                         uint32_t b0, uint32_t b1) {
    asm volatile(
        "mma.sync.aligned.m16n8k16.row.col.f32.f16.f16.f32 "
        "{%0,%1,%2,%3}, {%4,%5,%6,%7}, {%8,%9}, {%0,%1,%2,%3};"
        : "+f"(d[0]), "+f"(d[1]), "+f"(d[2]), "+f"(d[3])
        : "r"(a[0]), "r"(a[1]), "r"(a[2]), "r"(a[3]), "r"(b0), "r"(b1));
}

__device__ __forceinline__ float fast_tanh(float x) {
    x = fminf(fmaxf(x, -15.f), 15.f);
    float e = __expf(2.f * x);
    return __fdividef(e - 1.f, e + 1.f);
}

// ---------------- K0a: enc f32 -> fp16 --------------------------------------
__global__ void convert_enc_kernel(const float* __restrict__ enc) {
    size_t i = (size_t)blockIdx.x * 256 + threadIdx.x;   // one float4 per thread
    float4 x = ((const float4*)enc)[i];
    __half2 h01 = __floats2half2_rn(x.x, x.y);
    __half2 h23 = __floats2half2_rn(x.z, x.w);
    uint2 packed;
    packed.x = *(const uint32_t*)&h01;
    packed.y = *(const uint32_t*)&h23;
    ((uint2*)g_enc_hi)[i] = packed;
}

// ---------------- K0b: w_enc f32 -> fp16 ------------------------------------
__global__ void convert_w_kernel(const float* __restrict__ attn_w) {
    int idx = blockIdx.x * 256 + threadIdx.x;            // 262144
    int k = idx >> 9, h = idx & 511;
    float x = attn_w[(size_t)k * (2 * H_) + h];          // w_enc = attn_w[:, :H]
    g_w_hi[idx] = __float2half_rn(x);
}

// ---------------- K1: c[b,k] = fin[b]·attn_w[k, H:] + b[k] ------------------
__global__ void cfin_kernel(const float* __restrict__ fin,
                            const float* __restrict__ attn_w,
                            const float* __restrict__ attn_b) {
    __shared__ float fs[H_];
    const int b = blockIdx.x;
    const int k = threadIdx.x;
    fs[k] = fin[b * H_ + k];
    __syncthreads();
    const float* w = attn_w + (size_t)k * (2 * H_) + H_;
    float s = attn_b[k];
#pragma unroll 8
    for (int h = 0; h < H_; h++) s = fmaf(fs[h], w[h], s);
    g_c[b * H_ + k] = s;
}

// ---------------- K2: fp16 mma GEMM + tanh/v epilogue -----------------------
// CTA 128(s) x 256(k); 8 warps as 2(M) x 4(N); warp tile 64x64.
// K=512 in 8 chunks of 64; 3-stage cp.async; XOR swizzle; register epilogue.
static constexpr int KC = 64;                        // 64 fp16 = 128B rows
static constexpr int MAT_A  = 128 * 128;             // 16384 B (A: 128 x 64 fp16)
static constexpr int MAT_BT = 256 * 128;             // 32768 B (B: 256 x 64 fp16)
static constexpr int STAGE_B = MAT_A + MAT_BT;       // 49152
static constexpr int NSTAGE = 3;
static constexpr int CV_OFF = NSTAGE * STAGE_B;      // 147456
static constexpr int SMEM_NEED = CV_OFF + 2048;      // + c[256], v[256]

// physical byte offset of logical (row r, 16B-chunk c) inside a 128B-row tile
__device__ __forceinline__ uint32_t sw(int r, int c) {
    return (uint32_t)(r * 128 + (((c) ^ (r & 7)) << 4));
}

__device__ __forceinline__ void fill_chunk(uint32_t sbase, int stage, int ck,
                                           int mt, int kt, int tid) {
    const uint32_t tb = sbase + stage * STAGE_B;
    // A: 128 rows x 128B = 1024 cp16
#pragma unroll
    for (int i = 0; i < 4; i++) {
        int id = i * 256 + tid;          // 0..1023
        int r = id >> 3, c = id & 7;
        cp16(tb + sw(r, c),
             (const char*)g_enc_hi + (size_t)(mt * 128 + r) * 1024 + ck * 128 + c * 16);
    }
    // B: 256 rows x 128B = 2048 cp16
#pragma unroll
    for (int i = 0; i < 8; i++) {
        int id = i * 256 + tid;          // 0..2047
        int r = id >> 3, c = id & 7;
        cp16(tb + MAT_A + sw(r, c),
             (const char*)g_w_hi + (size_t)(kt * 256 + r) * 1024 + ck * 128 + c * 16);
    }
}

__global__ __launch_bounds__(256, 1)
void scores_mma_kernel(const float* __restrict__ v_w) {
    extern __shared__ char smem[];
    const uint32_t sbase = smem_u32(smem);
    const int tid = threadIdx.x;
    const int wid = tid >> 5, lane = tid & 31;
    const int kt = blockIdx.x;        // 0..1    (k half of 256)
    const int mt = blockIdx.y;        // 0..1023 (s tile of 128 over B*S)
    const int b  = mt >> 4;           // 16 s-tiles per batch
    const int wm = wid & 1;           // warp M index (2) -> 64 rows each
    const int wn = wid >> 1;          // warp N index (4) -> 64 cols each

    float* c_s = (float*)(smem + CV_OFF);
    float* v_s = (float*)(smem + CV_OFF + 1024);
    c_s[tid] = g_c[b * H_ + kt * 256 + tid];
    v_s[tid] = v_w[kt * 256 + tid];

    float acc[4][8][4];
#pragma unroll
    for (int i = 0; i < 4; i++)
#pragma unroll
        for (int j = 0; j < 8; j++)
#pragma unroll
            for (int t = 0; t < 4; t++) acc[i][j][t] = 0.f;

    fill_chunk(sbase, 0, 0, mt, kt, tid); CP_COMMIT();
    fill_chunk(sbase, 1, 1, mt, kt, tid); CP_COMMIT();

    const int lrow_a = wm * 64 + (lane & 15);
    const int lrow_b = wn * 64 + (lane & 15);
    const int lchi = lane >> 4;
    const int qv = lane & 7;
    uint32_t offv[4];
#pragma unroll
    for (int kk = 0; kk < 4; kk++) offv[kk] = (uint32_t)(((kk * 2 + lchi) ^ qv) << 4);

    int buf = 0;
    for (int ck = 0; ck < 8; ck++) {
        if (ck < 6) asm volatile("cp.async.wait_group 1;" ::: "memory");
        else        asm volatile("cp.async.wait_group 0;" ::: "memory");
        __syncthreads();
        if (ck + 2 < 8) {
            int nbuf = buf + 2; if (nbuf >= 3) nbuf -= 3;
            fill_chunk(sbase, nbuf, ck + 2, mt, kt, tid);
            CP_COMMIT();
        }

        const uint32_t stb = sbase + buf * STAGE_B;
        const uint32_t bA = stb + (uint32_t)(lrow_a * 128);
        const uint32_t bB = stb + MAT_A + (uint32_t)(lrow_b * 128);

#pragma unroll
        for (int kk = 0; kk < 4; kk++) {
            uint32_t a[4][4], bb[4][4];
#pragma unroll
            for (int i = 0; i < 4; i++) ldsm4(a[i], bA + i * 2048 + offv[kk]);
#pragma unroll
            for (int j = 0; j < 4; j++) ldsm4(bb[j], bB + j * 2048 + offv[kk]);
#pragma unroll
            for (int i = 0; i < 4; i++)
#pragma unroll
                for (int j = 0; j < 4; j++) {
                    mma16816(acc[i][j * 2 + 0], a[i], bb[j][0], bb[j][2]);
                    mma16816(acc[i][j * 2 + 1], a[i], bb[j][1], bb[j][3]);
                }
        }
        buf++; if (buf >= 3) buf = 0;
    }

    // ---- register epilogue: tanh(e + c) * v, quad-shuffle + smem reduce ----
    // thread holds rows {wm*64 + i*16 + (lane>>2), +8}, cols
    // {wn*64 + (j>>1)*16 + (j&1)*8 + (lane&3)*2 + {0,1}} for j in 0..7.
    float c_v[16], v_v[16];
#pragma unroll
    for (int j = 0; j < 8; j++) {
        const int col = wn * 64 + (j >> 1) * 16 + (j & 1) * 8 + (lane & 3) * 2;
        c_v[2 * j]     = c_s[col];
        c_v[2 * j + 1] = c_s[col + 1];
        v_v[2 * j]     = v_s[col];
        v_v[2 * j + 1] = v_s[col + 1];
    }
    float* red = (float*)smem;   // 128 rows x 4 wn = 2KB (stages dead)
    __syncthreads();
#pragma unroll
    for (int i = 0; i < 4; i++) {
        float p0 = 0.f, p1 = 0.f;
#pragma unroll
        for (int j = 0; j < 8; j++) {
            p0 += fast_tanh(acc[i][j][0] + c_v[2 * j])     * v_v[2 * j];
            p0 += fast_tanh(acc[i][j][1] + c_v[2 * j + 1]) * v_v[2 * j + 1];
            p1 += fast_tanh(acc[i][j][2] + c_v[2 * j])     * v_v[2 * j];
            p1 += fast_tanh(acc[i][j][3] + c_v[2 * j + 1]) * v_v[2 * j + 1];
        }
        p0 += __shfl_xor_sync(0xffffffffu, p0, 1);
        p0 += __shfl_xor_sync(0xffffffffu, p0, 2);
        p1 += __shfl_xor_sync(0xffffffffu, p1, 1);
        p1 += __shfl_xor_sync(0xffffffffu, p1, 2);
        if ((lane & 3) == 0) {
            const int r0 = wm * 64 + i * 16 + (lane >> 2);
            red[r0 * 4 + wn]       = p0;
            red[(r0 + 8) * 4 + wn] = p1;
        }
    }
    __syncthreads();
    if (tid < 128) {
        float s = red[tid * 4] + red[tid * 4 + 1] + red[tid * 4 + 2] + red[tid * 4 + 3];
        g_scores_part[(size_t)kt * (B_ * S_) + mt * 128 + tid] = s;
    }
}

// ---------------- K3: softmax over S per batch ------------------------------
__global__ void softmax_kernel() {
    const int b = blockIdx.x;
    const int tid = threadIdx.x;   // 256
    __shared__ float sbuf[256];

    float m = -1e30f;
    for (int i = tid; i < S_; i += 256) {
        float v = g_scores_part[0 * B_ * S_ + b * S_ + i]
                + g_scores_part[1 * B_ * S_ + b * S_ + i];
        g_weights[b * S_ + i] = v;
        m = fmaxf(m, v);
    }
    sbuf[tid] = m; __syncthreads();
    for (int o = 128; o > 0; o >>= 1) {
        if (tid < o) sbuf[tid] = fmaxf(sbuf[tid], sbuf[tid + o]);
        __syncthreads();
    }
    m = sbuf[0]; __syncthreads();

    float sum = 0.f;
    for (int i = tid; i < S_; i += 256) {
        float e = __expf(g_weights[b * S_ + i] - m);
        g_weights[b * S_ + i] = e;
        sum += e;
    }
    sbuf[tid] = sum; __syncthreads();
    for (int o = 128; o > 0; o >>= 1) {
        if (tid < o) sbuf[tid] += sbuf[tid + o];
        __syncthreads();
    }
    float inv = __fdividef(1.f, sbuf[0]);
    for (int i = tid; i < S_; i += 256) g_weights[b * S_ + i] *= inv;
}

// ---------------- K4: partial context per 128-s chunk (fp16 enc) ------------
__global__ void context_kernel() {
    const int sc = blockIdx.x;   // 0..15
    const int b  = blockIdx.y;
    const int tid = threadIdx.x; // 256, each handles 2 h columns
    __shared__ float ws[128];
    if (tid < 128) ws[tid] = g_weights[b * S_ + sc * 128 + tid];
    __syncthreads();
    const __half2* e = (const __half2*)(g_enc_hi + ((size_t)b * S_ + sc * 128) * H_) + tid;
    float ax = 0.f, ay = 0.f;
#pragma unroll 8
    for (int s = 0; s < 128; s++) {
        float2 v = __half22float2(e[(size_t)s * (H_ / 2)]);
        ax = fmaf(ws[s], v.x, ax);
        ay = fmaf(ws[s], v.y, ay);
    }
    float* dst = &g_ctx_part[((size_t)sc * B_ + b) * H_ + 2 * tid];
    dst[0] = ax;
    dst[1] = ay;
}

// ---------------- K5: reduce partial contexts -------------------------------
__global__ void reduce_ctx(float* __restrict__ out) {
    int i = blockIdx.x * 256 + threadIdx.x;
    float s = 0.f;
#pragma unroll
    for (int ch = 0; ch < 16; ch++) s += g_ctx_part[(size_t)ch * B_ * H_ + i];
    out[i] = s;
}

extern "C" void kernel_launch(void* const* d_in, const int* in_sizes, int n_in,
                              void* d_out, int out_size) {
    const float* enc    = (const float*)d_in[0];
    const float* fin    = (const float*)d_in[1];
    const float* attn_w = (const float*)d_in[2];
    const float* attn_b = (const float*)d_in[3];
    const float* v_w    = (const float*)d_in[4];
    float* out = (float*)d_out;

    cudaFuncSetAttribute(scores_mma_kernel,
                         cudaFuncAttributeMaxDynamicSharedMemorySize, SMEM_NEED);

    convert_enc_kernel<<<65536, 256>>>(enc);
    convert_w_kernel<<<(H_ * H_) / 256, 256>>>(attn_w);
    cfin_kernel<<<B_, H_>>>(fin, attn_w, attn_b);
    scores_mma_kernel<<<dim3(2, 1024), 256, SMEM_NEED>>>(v_w);
    softmax_kernel<<<B_, 256>>>();
    context_kernel<<<dim3(16, B_), 256>>>();
    reduce_ctx<<<(B_ * H_) / 256, 256>>>(out);
}

// round 15
// speedup vs baseline: 1.9328x; 1.0126x over previous
#include <cuda_runtime.h>
#include <cuda_fp16.h>
#include <cstdint>

#define B_ 64
#define S_ 2048
#define H_ 512

// ---------------- scratch (device globals; no allocation allowed) ----------
__device__ float g_c[B_ * H_];                       // e_fin[b,k] + attn_b[k]
__device__ float g_scores_part[2 * B_ * S_];         // per-k-half partial scores
__device__ float g_weights[B_ * S_];                 // softmax weights
__device__ float g_ctx_part[16 * B_ * H_];           // per-s-chunk partial context
__device__ __half g_enc_hi[(size_t)B_ * S_ * H_];    // 128 MB (fp16)
__device__ __half g_w_hi[H_ * H_];

// ---------------- helpers ---------------------------------------------------
__device__ __forceinline__ uint32_t smem_u32(const void* p) {
    uint32_t a;
    asm("{ .reg .u64 t; cvta.to.shared.u64 t, %1; cvt.u32.u64 %0, t; }" : "=r"(a) : "l"(p));
    return a;
}
__device__ __forceinline__ void cp16(uint32_t dst, const void* src) {
    asm volatile("cp.async.cg.shared.global [%0], [%1], 16;" :: "r"(dst), "l"(src) : "memory");
}
#define CP_COMMIT() asm volatile("cp.async.commit_group;" ::: "memory")

__device__ __forceinline__ void ldsm4(uint32_t* r, uint32_t addr) {
    asm volatile("ldmatrix.sync.aligned.m8n8.x4.shared.b16 {%0,%1,%2,%3}, [%4];"
                 : "=r"(r[0]), "=r"(r[1]), "=r"(r[2]), "=r"(r[3]) : "r"(addr));
}
__device__ __forceinline__ void mma16816(float* d, const uint32_t* a,
                                         uint32_t b0, uint32_t b1) {
    asm volatile(
        "mma.sync.aligned.m16n8k16.row.col.f32.f16.f16.f32 "
        "{%0,%1,%2,%3}, {%4,%5,%6,%7}, {%8,%9}, {%0,%1,%2,%3};"
        : "+f"(d[0]), "+f"(d[1]), "+f"(d[2]), "+f"(d[3])
        : "r"(a[0]), "r"(a[1]), "r"(a[2]), "r"(a[3]), "r"(b0), "r"(b1));
}

__device__ __forceinline__ float fast_tanh(float x) {
    x = fminf(fmaxf(x, -15.f), 15.f);
    float e = __expf(2.f * x);
    return __fdividef(e - 1.f, e + 1.f);
}

// ---------------- K0a: enc f32 -> fp16 --------------------------------------
__global__ void convert_enc_kernel(const float* __restrict__ enc) {
    size_t i = (size_t)blockIdx.x * 256 + threadIdx.x;   // one float4 per thread
    float4 x = ((const float4*)enc)[i];
    __half2 h01 = __floats2half2_rn(x.x, x.y);
    __half2 h23 = __floats2half2_rn(x.z, x.w);
    uint2 packed;
    packed.x = *(const uint32_t*)&h01;
    packed.y = *(const uint32_t*)&h23;
    ((uint2*)g_enc_hi)[i] = packed;
}

// ---------------- K0b: w_enc f32 -> fp16 ------------------------------------
__global__ void convert_w_kernel(const float* __restrict__ attn_w) {
    int idx = blockIdx.x * 256 + threadIdx.x;            // 262144
    int k = idx >> 9, h = idx & 511;
    float x = attn_w[(size_t)k * (2 * H_) + h];          // w_enc = attn_w[:, :H]
    g_w_hi[idx] = __float2half_rn(x);
}

// ---------------- K1: c[b,k] = fin[b]·attn_w[k, H:] + b[k] ------------------
__global__ void cfin_kernel(const float* __restrict__ fin,
                            const float* __restrict__ attn_w,
                            const float* __restrict__ attn_b) {
    __shared__ float fs[H_];
    const int b = blockIdx.x;
    const int k = threadIdx.x;
    fs[k] = fin[b * H_ + k];
    __syncthreads();
    const float* w = attn_w + (size_t)k * (2 * H_) + H_;
    float s = attn_b[k];
#pragma unroll 8
    for (int h = 0; h < H_; h++) s = fmaf(fs[h], w[h], s);
    g_c[b * H_ + k] = s;
}

// ---------------- K2: fp16 mma GEMM + tanh/v epilogue -----------------------
// CTA 128(s) x 256(k); 8 warps as 2(M) x 4(N); warp tile 64x64.
// K=512 in 8 chunks of 64; 3-stage cp.async, FULLY UNROLLED mainloop with
// compile-time stages, hoisted fill addressing, fills interleaved into kk.
static constexpr int KC = 64;                        // 64 fp16 = 128B rows
static constexpr int MAT_A  = 128 * 128;             // 16384 B (A: 128 x 64 fp16)
static constexpr int MAT_BT = 256 * 128;             // 32768 B (B: 256 x 64 fp16)
static constexpr int STAGE_B = MAT_A + MAT_BT;       // 49152
static constexpr int NSTAGE = 3;
static constexpr int CV_OFF = NSTAGE * STAGE_B;      // 147456
static constexpr int SMEM_NEED = CV_OFF + 2048;      // + c[256], v[256]

// physical byte offset of logical (row r, 16B-chunk c) inside a 128B-row tile
__device__ __forceinline__ uint32_t sw(int r, int c) {
    return (uint32_t)(r * 128 + (((c) ^ (r & 7)) << 4));
}

__global__ __launch_bounds__(256, 1)
void scores_mma_kernel(const float* __restrict__ v_w) {
    extern __shared__ char smem[];
    const uint32_t sbase = smem_u32(smem);
    const int tid = threadIdx.x;
    const int wid = tid >> 5, lane = tid & 31;
    const int kt = blockIdx.x;        // 0..1    (k half of 256)
    const int mt = blockIdx.y;        // 0..1023 (s tile of 128 over B*S)
    const int b  = mt >> 4;           // 16 s-tiles per batch
    const int wm = wid & 1;           // warp M index (2) -> 64 rows each
    const int wn = wid >> 1;          // warp N index (4) -> 64 cols each

    float* c_s = (float*)(smem + CV_OFF);
    float* v_s = (float*)(smem + CV_OFF + 1024);
    c_s[tid] = g_c[b * H_ + kt * 256 + tid];
    v_s[tid] = v_w[kt * 256 + tid];

    float acc[4][8][4];
#pragma unroll
    for (int i = 0; i < 4; i++)
#pragma unroll
        for (int j = 0; j < 8; j++)
#pragma unroll
            for (int t = 0; t < 4; t++) acc[i][j][t] = 0.f;

    // ---- hoisted per-thread fill addressing (chunk-invariant) --------------
    uint32_t sA_off[4], gA_off[4];    // A: 4 cp16 per thread per chunk
    uint32_t sB_off[8], gB_off[8];    // B: 8 cp16 per thread per chunk
#pragma unroll
    for (int i = 0; i < 4; i++) {
        int id = i * 256 + tid;
        int r = id >> 3, c = id & 7;
        sA_off[i] = sw(r, c);
        gA_off[i] = (uint32_t)(r * 1024 + c * 16);
    }
#pragma unroll
    for (int i = 0; i < 8; i++) {
        int id = i * 256 + tid;
        int r = id >> 3, c = id & 7;
        sB_off[i] = (uint32_t)MAT_A + sw(r, c);
        gB_off[i] = (uint32_t)(r * 1024 + c * 16);
    }
    const char* gA = (const char*)g_enc_hi + (size_t)mt * 128 * 1024;
    const char* gB = (const char*)g_w_hi + (size_t)kt * 256 * 1024;

    // fill part p (0..3) of chunk ck into stage st: 1 A + 2 B cp16
#define FILL_PART(st, ck, p)                                                    \
    do {                                                                        \
        cp16(sbase + (st) * STAGE_B + sA_off[p], gA + gA_off[p] + (ck) * 128);  \
        cp16(sbase + (st) * STAGE_B + sB_off[2 * (p)],                          \
             gB + gB_off[2 * (p)] + (ck) * 128);                                \
        cp16(sbase + (st) * STAGE_B + sB_off[2 * (p) + 1],                      \
             gB + gB_off[2 * (p) + 1] + (ck) * 128);                            \
    } while (0)

    // prologue: chunks 0 and 1
#pragma unroll
    for (int p = 0; p < 4; p++) FILL_PART(0, 0, p);
    CP_COMMIT();
#pragma unroll
    for (int p = 0; p < 4; p++) FILL_PART(1, 1, p);
    CP_COMMIT();

    const int lrow_a = wm * 64 + (lane & 15);
    const int lrow_b = wn * 64 + (lane & 15);
    const int lchi = lane >> 4;
    const int qv = lane & 7;
    uint32_t offv[4];
#pragma unroll
    for (int kk = 0; kk < 4; kk++) offv[kk] = (uint32_t)(((kk * 2 + lchi) ^ qv) << 4);

#pragma unroll
    for (int ck = 0; ck < 8; ck++) {
        const int buf  = ck % 3;            // compile-time after unroll
        const int nbuf = (ck + 2) % 3;
        if (ck < 6) asm volatile("cp.async.wait_group 1;" ::: "memory");
        else        asm volatile("cp.async.wait_group 0;" ::: "memory");
        __syncthreads();

        const uint32_t stb = sbase + buf * STAGE_B;
        const uint32_t bA = stb + (uint32_t)(lrow_a * 128);
        const uint32_t bB = stb + (uint32_t)MAT_A + (uint32_t)(lrow_b * 128);

#pragma unroll
        for (int kk = 0; kk < 4; kk++) {
            uint32_t a[4][4], bb[4][4];
#pragma unroll
            for (int i = 0; i < 4; i++) ldsm4(a[i], bA + i * 2048 + offv[kk]);
#pragma unroll
            for (int j = 0; j < 4; j++) ldsm4(bb[j], bB + j * 2048 + offv[kk]);
#pragma unroll
            for (int i = 0; i < 4; i++)
#pragma unroll
                for (int j = 0; j < 4; j++) {
                    mma16816(acc[i][j * 2 + 0], a[i], bb[j][0], bb[j][2]);
                    mma16816(acc[i][j * 2 + 1], a[i], bb[j][1], bb[j][3]);
                }
            if (ck + 2 < 8) {
                FILL_PART(nbuf, ck + 2, kk);      // 3 cp.async per kk group
                if (kk == 3) CP_COMMIT();
            }
        }
    }
#undef FILL_PART

    // ---- register epilogue: tanh(e + c) * v, quad-shuffle + smem reduce ----
    // thread holds rows {wm*64 + i*16 + (lane>>2), +8}, cols
    // {wn*64 + (j>>1)*16 + (j&1)*8 + (lane&3)*2 + {0,1}} for j in 0..7.
    float c_v[16], v_v[16];
#pragma unroll
    for (int j = 0; j < 8; j++) {
        const int col = wn * 64 + (j >> 1) * 16 + (j & 1) * 8 + (lane & 3) * 2;
        c_v[2 * j]     = c_s[col];
        c_v[2 * j + 1] = c_s[col + 1];
        v_v[2 * j]     = v_s[col];
        v_v[2 * j + 1] = v_s[col + 1];
    }
    float* red = (float*)smem;   // 128 rows x 4 wn = 2KB (stages dead)
    __syncthreads();
#pragma unroll
    for (int i = 0; i < 4; i++) {
        float p0 = 0.f, p1 = 0.f;
#pragma unroll
        for (int j = 0; j < 8; j++) {
            p0 += fast_tanh(acc[i][j][0] + c_v[2 * j])     * v_v[2 * j];
            p0 += fast_tanh(acc[i][j][1] + c_v[2 * j + 1]) * v_v[2 * j + 1];
            p1 += fast_tanh(acc[i][j][2] + c_v[2 * j])     * v_v[2 * j];
            p1 += fast_tanh(acc[i][j][3] + c_v[2 * j + 1]) * v_v[2 * j + 1];
        }
        p0 += __shfl_xor_sync(0xffffffffu, p0, 1);
        p0 += __shfl_xor_sync(0xffffffffu, p0, 2);
        p1 += __shfl_xor_sync(0xffffffffu, p1, 1);
        p1 += __shfl_xor_sync(0xffffffffu, p1, 2);
        if ((lane & 3) == 0) {
            const int r0 = wm * 64 + i * 16 + (lane >> 2);
            red[r0 * 4 + wn]       = p0;
            red[(r0 + 8) * 4 + wn] = p1;
        }
    }
    __syncthreads();
    if (tid < 128) {
        float s = red[tid * 4] + red[tid * 4 + 1] + red[tid * 4 + 2] + red[tid * 4 + 3];
        g_scores_part[(size_t)kt * (B_ * S_) + mt * 128 + tid] = s;
    }
}

// ---------------- K3: softmax over S per batch ------------------------------
__global__ void softmax_kernel() {
    const int b = blockIdx.x;
    const int tid = threadIdx.x;   // 256
    __shared__ float sbuf[256];

    float m = -1e30f;
    for (int i = tid; i < S_; i += 256) {
        float v = g_scores_part[0 * B_ * S_ + b * S_ + i]
                + g_scores_part[1 * B_ * S_ + b * S_ + i];
        g_weights[b * S_ + i] = v;
        m = fmaxf(m, v);
    }
    sbuf[tid] = m; __syncthreads();
    for (int o = 128; o > 0; o >>= 1) {
        if (tid < o) sbuf[tid] = fmaxf(sbuf[tid], sbuf[tid + o]);
        __syncthreads();
    }
    m = sbuf[0]; __syncthreads();

    float sum = 0.f;
    for (int i = tid; i < S_; i += 256) {
        float e = __expf(g_weights[b * S_ + i] - m);
        g_weights[b * S_ + i] = e;
        sum += e;
    }
    sbuf[tid] = sum; __syncthreads();
    for (int o = 128; o > 0; o >>= 1) {
        if (tid < o) sbuf[tid] += sbuf[tid + o];
        __syncthreads();
    }
    float inv = __fdividef(1.f, sbuf[0]);
    for (int i = tid; i < S_; i += 256) g_weights[b * S_ + i] *= inv;
}

// ---------------- K4: partial context per 128-s chunk (fp16 enc) ------------
__global__ void context_kernel() {
    const int sc = blockIdx.x;   // 0..15
    const int b  = blockIdx.y;
    const int tid = threadIdx.x; // 256, each handles 2 h columns
    __shared__ float ws[128];
    if (tid < 128) ws[tid] = g_weights[b * S_ + sc * 128 + tid];
    __syncthreads();
    const __half2* e = (const __half2*)(g_enc_hi + ((size_t)b * S_ + sc * 128) * H_) + tid;
    float ax = 0.f, ay = 0.f;
#pragma unroll 8
    for (int s = 0; s < 128; s++) {
        float2 v = __half22float2(e[(size_t)s * (H_ / 2)]);
        ax = fmaf(ws[s], v.x, ax);
        ay = fmaf(ws[s], v.y, ay);
    }
    float* dst = &g_ctx_part[((size_t)sc * B_ + b) * H_ + 2 * tid];
    dst[0] = ax;
    dst[1] = ay;
}

// ---------------- K5: reduce partial contexts -------------------------------
__global__ void reduce_ctx(float* __restrict__ out) {
    int i = blockIdx.x * 256 + threadIdx.x;
    float s = 0.f;
#pragma unroll
    for (int ch = 0; ch < 16; ch++) s += g_ctx_part[(size_t)ch * B_ * H_ + i];
    out[i] = s;
}

extern "C" void kernel_launch(void* const* d_in, const int* in_sizes, int n_in,
                              void* d_out, int out_size) {
    const float* enc    = (const float*)d_in[0];
    const float* fin    = (const float*)d_in[1];
    const float* attn_w = (const float*)d_in[2];
    const float* attn_b = (const float*)d_in[3];
    const float* v_w    = (const float*)d_in[4];
    float* out = (float*)d_out;

    cudaFuncSetAttribute(scores_mma_kernel,
                         cudaFuncAttributeMaxDynamicSharedMemorySize, SMEM_NEED);

    convert_enc_kernel<<<65536, 256>>>(enc);
    convert_w_kernel<<<(H_ * H_) / 256, 256>>>(attn_w);
    cfin_kernel<<<B_, H_>>>(fin, attn_w, attn_b);
    scores_mma_kernel<<<dim3(2, 1024), 256, SMEM_NEED>>>(v_w);
    softmax_kernel<<<B_, 256>>>();
    context_kernel<<<dim3(16, B_), 256>>>();
    reduce_ctx<<<(B_ * H_) / 256, 256>>>(out);
}